// round 16
// baseline (speedup 1.0000x reference)
#include <cuda_runtime.h>

// Problem constants
#define BB   4
#define CC   64
#define NN   4096              // H*W
#define ROWS (BB*NN)           // 16384

#define GRID 296               // exactly 2 CTAs per SM on 148-SM GB300
#define TPB  256
#define NV   (ROWS*CC/4)       // 262144 float4
#define STRIDE (GRID*TPB)      // 75776

// ---------------- scratch (device globals: allocation-free) ----------------
__device__ __align__(16) float g_qs[ROWS*CC];
__device__ __align__(16) float g_ks[ROWS*CC];
__device__ __align__(16) float g_vs[ROWS*CC];
__device__ __align__(16) float g_qc[ROWS*CC];
__device__ __align__(16) float g_kc[ROWS*CC];
__device__ __align__(16) float g_vc[ROWS*CC];
__device__ __align__(16) float g_spat[ROWS*CC];
__device__ __align__(16) float g_chan[ROWS*CC];

// software grid barrier state (persists across graph replays: release is
// a monotonic generation counter, arrive resets to 0 every barrier)
__device__ unsigned int g_arrive  = 0;
__device__ unsigned int g_release = 0;

__device__ __forceinline__ void grid_sync()
{
    __syncthreads();
    if (threadIdx.x == 0) {
        const unsigned int gen = atomicAdd(&g_release, 0u);   // snapshot BEFORE arriving
        __threadfence();                                      // publish block's writes
        if (atomicAdd(&g_arrive, 1u) == GRID - 1) {
            atomicExch(&g_arrive, 0u);
            __threadfence();
            atomicAdd(&g_release, 1u);                        // release everyone
        } else {
            while (atomicAdd(&g_release, 0u) == gen) { __nanosleep(64); }
        }
        __threadfence();                                      // acquire side
    }
    __syncthreads();
}

// ---------------- shared memory union (max ~33 KB) ----------------
union SmemU {
    struct {                       // projections
        float sx[64][CC];          // 16 KB
        float sw[CC][CC];          // 16 KB
        float sb[CC];
    } pr;
    struct {                       // spatial flash attention (32x32 tiles)
        float sQ[32][CC];          // 8 KB
        float sK[32][CC + 1];      // 8.125 KB
        float sV[32][CC];          // 8 KB
        float sS[32][33];          // 4.125 KB
        float sm[32], sl[32], sfac[32];
    } sp;
    struct {                       // channel attention
        float sq[CC][33];          // 8.25 KB (also reused for V tile)
        float sk[CC][33];          // 8.25 KB
        float satt[CC][CC + 1];    // 16.25 KB
    } ch;
};

// ---------------------------------------------------------------------------
__global__ void __launch_bounds__(TPB, 2)
pcam_fused(const float* __restrict__ x,
           const float* __restrict__ wqs, const float* __restrict__ bqs,
           const float* __restrict__ wks, const float* __restrict__ bks,
           const float* __restrict__ wvs, const float* __restrict__ bvs,
           const float* __restrict__ wqc, const float* __restrict__ bqc,
           const float* __restrict__ wkc, const float* __restrict__ bkc,
           const float* __restrict__ wvc, const float* __restrict__ bvc,
           const float* __restrict__ ga, const float* __restrict__ gb,
           float* __restrict__ out)
{
    const int t   = threadIdx.x;
    const int bid = blockIdx.x;
    const int tid = bid * TPB + t;      // 0..75775

    __shared__ float s_gates[2];

    // ONE thread per block reads the gate scalars (592 same-address L2
    // requests chip-wide instead of ~4700 warp-level ones), while every
    // thread's copy stream proceeds gate-independently below.
    if (t == 0) {
        s_gates[0] = __ldg(ga);
        s_gates[1] = __ldg(gb);
    }

    const float4* __restrict__ x4 = reinterpret_cast<const float4*>(x);
    float4* __restrict__ o4 = reinterpret_cast<float4*>(out);

    // Gate-independent speculative copy: out = 2x, issued before the gates
    // are even known. k=0..2 always in range (227327 < NV); k=3 partial.
    const bool p3 = (tid + 3 * STRIDE) < NV;
    const float4 v0 = x4[tid];
    const float4 v1 = x4[tid + STRIDE];
    const float4 v2 = x4[tid + 2 * STRIDE];
    const float4 v3 = p3 ? x4[tid + 3 * STRIDE] : make_float4(0.f, 0.f, 0.f, 0.f);

    // SPECULATIVE STORE: if gates are nonzero, the heavy path's fuse phase
    // overwrites every element; nothing reads `out` in between.
    __stwt(&o4[tid],              make_float4(2.f*v0.x, 2.f*v0.y, 2.f*v0.z, 2.f*v0.w));
    __stwt(&o4[tid + STRIDE],     make_float4(2.f*v1.x, 2.f*v1.y, 2.f*v1.z, 2.f*v1.w));
    __stwt(&o4[tid + 2 * STRIDE], make_float4(2.f*v2.x, 2.f*v2.y, 2.f*v2.z, 2.f*v2.w));
    if (p3)
        __stwt(&o4[tid + 3 * STRIDE], make_float4(2.f*v3.x, 2.f*v3.y, 2.f*v3.z, 2.f*v3.w));

    // Resolve gates via shared-memory broadcast (cheap, off the store path).
    __syncthreads();
    const float av = s_gates[0];
    const float bv = s_gates[1];
    const bool need_s = (bv != 0.0f);
    const bool need_c = (av != 0.0f);
    if (!need_s && !need_c) return;     // fast path done

    // ======================= HEAVY PATH ====================================
    __shared__ SmemU u;

    // ---- Phase 1: six 1x1-conv projections, y = x @ W + bias -------------
    {
        const float* Ws[6] = {wqs, wks, wvs, wqc, wkc, wvc};
        const float* Bs[6] = {bqs, bks, bvs, bqc, bkc, bvc};
        float* Os[6] = {g_qs, g_ks, g_vs, g_qc, g_kc, g_vc};

        const int d  = t & 63;
        const int r0 = t >> 6;

        for (int chunk = bid; chunk < ROWS / 64; chunk += GRID) {
            const int row0 = chunk * 64;
            __syncthreads();
            for (int i = t; i < 64 * CC; i += TPB)
                u.pr.sx[i / CC][i % CC] = x[row0 * CC + i];

            for (int p = 0; p < 6; p++) {
                const bool need = (p < 3) ? need_s : need_c;   // uniform
                if (!need) continue;
                __syncthreads();
                for (int i = t; i < CC * CC; i += TPB)
                    u.pr.sw[i / CC][i % CC] = Ws[p][i];
                if (t < CC) u.pr.sb[t] = Bs[p][t];
                __syncthreads();
                #pragma unroll
                for (int i = 0; i < 16; i++) {
                    const int r = r0 + 4 * i;
                    float s = u.pr.sb[d];
                    #pragma unroll
                    for (int c = 0; c < CC; c++)
                        s = fmaf(u.pr.sx[r][c], u.pr.sw[c][d], s);
                    Os[p][(row0 + r) * CC + d] = s;
                }
            }
        }
    }
    grid_sync();

    // ---- Phase 2a: spatial flash attention (512 tiles of 32 rows) --------
    if (need_s) {
        const int kS  = t & 31;
        const int rS0 = t >> 5;
        const int dO  = t & 63;
        const int rO0 = t >> 6;

        for (int tile = bid; tile < (NN / 32) * BB; tile += GRID) {
            const int bb    = tile >> 7;           // tile / 128
            const int rbase = (tile & 127) * 32;
            const float* Qg = g_qs + (bb * NN + rbase) * CC;
            const float* Kg = g_ks + bb * NN * CC;
            const float* Vg = g_vs + bb * NN * CC;

            __syncthreads();
            for (int i = t; i < 32 * CC; i += TPB)
                u.sp.sQ[i / CC][i % CC] = Qg[i];
            if (t < 32) { u.sp.sm[t] = -1e30f; u.sp.sl[t] = 0.0f; }

            float accO[8];
            #pragma unroll
            for (int i = 0; i < 8; i++) accO[i] = 0.0f;
            __syncthreads();

            for (int k0 = 0; k0 < NN; k0 += 32) {
                for (int i = t; i < 32 * CC; i += TPB) {
                    const int kr = i / CC, c = i % CC;
                    u.sp.sK[kr][c] = Kg[(k0 + kr) * CC + c];
                    u.sp.sV[kr][c] = Vg[(k0 + kr) * CC + c];
                }
                __syncthreads();

                #pragma unroll
                for (int i = 0; i < 4; i++) {
                    const int r = rS0 + 8 * i;
                    float s = 0.0f;
                    #pragma unroll
                    for (int c = 0; c < CC; c++)
                        s = fmaf(u.sp.sQ[r][c], u.sp.sK[kS][c], s);
                    u.sp.sS[r][kS] = s * 0.125f;
                }
                __syncthreads();

                if (t < 32) {
                    float mx = u.sp.sm[t];
                    #pragma unroll
                    for (int k = 0; k < 32; k++) mx = fmaxf(mx, u.sp.sS[t][k]);
                    const float fac = __expf(u.sp.sm[t] - mx);
                    float lsum = u.sp.sl[t] * fac;
                    #pragma unroll
                    for (int k = 0; k < 32; k++) {
                        const float p = __expf(u.sp.sS[t][k] - mx);
                        u.sp.sS[t][k] = p;
                        lsum += p;
                    }
                    u.sp.sm[t] = mx; u.sp.sl[t] = lsum; u.sp.sfac[t] = fac;
                }
                __syncthreads();

                #pragma unroll
                for (int i = 0; i < 8; i++) {
                    const int r = rO0 + 4 * i;
                    float s = 0.0f;
                    #pragma unroll
                    for (int k = 0; k < 32; k++)
                        s = fmaf(u.sp.sS[r][k], u.sp.sV[k][dO], s);
                    accO[i] = accO[i] * u.sp.sfac[r] + s;
                }
                __syncthreads();
            }

            #pragma unroll
            for (int i = 0; i < 8; i++) {
                const int r = rO0 + 4 * i;
                g_spat[(bb * NN + rbase + r) * CC + dO] = accO[i] / u.sp.sl[r];
            }
        }
    }

    // ---- Phase 2b: channel attention (one block per batch) ---------------
    if (need_c && bid < BB) {
        const int bb = bid;
        const float* qc = g_qc + bb * NN * CC;
        const float* kc = g_kc + bb * NN * CC;
        const float* vc = g_vc + bb * NN * CC;
        float* chan = g_chan + bb * NN * CC;

        const int d  = t & 63;
        const int c0 = t >> 6;

        float acc[16];
        #pragma unroll
        for (int i = 0; i < 16; i++) acc[i] = 0.0f;

        // Gram: G[c][d] = sum_n qc[c,n] * kc[d,n]
        for (int n0 = 0; n0 < NN; n0 += 32) {
            __syncthreads();
            for (int i = t; i < CC * 32; i += TPB) {
                const int c = i >> 5, j = i & 31;
                u.ch.sq[c][j] = qc[c * NN + n0 + j];
                u.ch.sk[c][j] = kc[c * NN + n0 + j];
            }
            __syncthreads();
            #pragma unroll
            for (int i = 0; i < 16; i++) {
                const int c = c0 + 4 * i;
                float s = 0.0f;
                #pragma unroll
                for (int j = 0; j < 32; j++)
                    s = fmaf(u.ch.sq[c][j], u.ch.sk[d][j], s);
                acc[i] += s;
            }
        }
        __syncthreads();
        #pragma unroll
        for (int i = 0; i < 16; i++) u.ch.satt[c0 + 4 * i][d] = acc[i] * 0.125f;
        __syncthreads();

        if (t < CC) {
            float mx = -1e30f;
            for (int dd = 0; dd < CC; dd++) mx = fmaxf(mx, u.ch.satt[t][dd]);
            float sum = 0.0f;
            for (int dd = 0; dd < CC; dd++) {
                const float p = __expf(u.ch.satt[t][dd] - mx);
                u.ch.satt[t][dd] = p; sum += p;
            }
            const float inv = 1.0f / sum;
            for (int dd = 0; dd < CC; dd++) u.ch.satt[t][dd] *= inv;
        }
        __syncthreads();

        const int j   = t & 31;
        const int c0b = t >> 5;
        for (int n0 = 0; n0 < NN; n0 += 32) {
            __syncthreads();
            for (int i = t; i < CC * 32; i += TPB) {
                const int dd = i >> 5, jj = i & 31;
                u.ch.sq[dd][jj] = vc[dd * NN + n0 + jj];
            }
            __syncthreads();
            #pragma unroll
            for (int i = 0; i < 8; i++) {
                const int c = c0b + 8 * i;
                float s = 0.0f;
                #pragma unroll
                for (int dd = 0; dd < CC; dd++)
                    s = fmaf(u.ch.satt[c][dd], u.ch.sq[dd][j], s);
                chan[c * NN + n0 + j] = s;
            }
        }
    }
    grid_sync();

    // ---- Phase 3: fuse out = 2x + b*spat + a*chan -------------------------
    // Overwrites the speculative 2x stores with the full result.
    // (channel's raw (B,C,N)->(B,H,W,C) reshape is a flat no-op)
    const float4* s4 = reinterpret_cast<const float4*>(g_spat);
    const float4* c4 = reinterpret_cast<const float4*>(g_chan);
    #pragma unroll
    for (int k = 0; k < 4; k++) {
        const int i = tid + k * STRIDE;
        if (i >= NV) break;
        const float4 xv = x4[i];
        float4 o = make_float4(2.0f * xv.x, 2.0f * xv.y, 2.0f * xv.z, 2.0f * xv.w);
        if (need_s) {
            const float4 s = s4[i];
            o.x += bv * s.x; o.y += bv * s.y; o.z += bv * s.z; o.w += bv * s.w;
        }
        if (need_c) {
            const float4 c = c4[i];
            o.x += av * c.x; o.y += av * c.y; o.z += av * c.z; o.w += av * c.w;
        }
        __stwt(&o4[i], o);
    }
}

// ---------------------------------------------------------------------------
extern "C" void kernel_launch(void* const* d_in, const int* in_sizes, int n_in,
                              void* d_out, int out_size)
{
    const float* x   = (const float*)d_in[0];
    const float* wqs = (const float*)d_in[1];  const float* bqs = (const float*)d_in[2];
    const float* wks = (const float*)d_in[3];  const float* bks = (const float*)d_in[4];
    const float* wvs = (const float*)d_in[5];  const float* bvs = (const float*)d_in[6];
    const float* wqc = (const float*)d_in[7];  const float* bqc = (const float*)d_in[8];
    const float* wkc = (const float*)d_in[9];  const float* bkc = (const float*)d_in[10];
    const float* wvc = (const float*)d_in[11]; const float* bvc = (const float*)d_in[12];
    const float* ga  = (const float*)d_in[13];
    const float* gb  = (const float*)d_in[14];

    pcam_fused<<<GRID, TPB>>>(x, wqs, bqs, wks, bks, wvs, bvs,
                              wqc, bqc, wkc, bkc, wvc, bvc,
                              ga, gb, (float*)d_out);
}

// round 17
// speedup vs baseline: 1.0435x; 1.0435x over previous
#include <cuda_runtime.h>

// Problem constants
#define BB   4
#define CC   64
#define NN   4096              // H*W
#define ROWS (BB*NN)           // 16384

#define GRID 296               // exactly 2 CTAs per SM on 148-SM GB300
#define TPB  256
#define NV   (ROWS*CC/4)       // 262144 float4
#define STRIDE (GRID*TPB)      // 75776

// ---------------- scratch (device globals: allocation-free) ----------------
__device__ __align__(16) float g_qs[ROWS*CC];
__device__ __align__(16) float g_ks[ROWS*CC];
__device__ __align__(16) float g_vs[ROWS*CC];
__device__ __align__(16) float g_qc[ROWS*CC];
__device__ __align__(16) float g_kc[ROWS*CC];
__device__ __align__(16) float g_vc[ROWS*CC];
__device__ __align__(16) float g_spat[ROWS*CC];
__device__ __align__(16) float g_chan[ROWS*CC];

// software grid barrier state (persists across graph replays: release is
// a monotonic generation counter, arrive resets to 0 every barrier)
__device__ unsigned int g_arrive  = 0;
__device__ unsigned int g_release = 0;

__device__ __forceinline__ void grid_sync()
{
    __syncthreads();
    if (threadIdx.x == 0) {
        const unsigned int gen = atomicAdd(&g_release, 0u);   // snapshot BEFORE arriving
        __threadfence();                                      // publish block's writes
        if (atomicAdd(&g_arrive, 1u) == GRID - 1) {
            atomicExch(&g_arrive, 0u);
            __threadfence();
            atomicAdd(&g_release, 1u);                        // release everyone
        } else {
            while (atomicAdd(&g_release, 0u) == gen) { __nanosleep(64); }
        }
        __threadfence();                                      // acquire side
    }
    __syncthreads();
}

// ---------------- shared memory union (max ~33 KB) ----------------
union SmemU {
    struct {                       // projections
        float sx[64][CC];          // 16 KB
        float sw[CC][CC];          // 16 KB
        float sb[CC];
    } pr;
    struct {                       // spatial flash attention (32x32 tiles)
        float sQ[32][CC];          // 8 KB
        float sK[32][CC + 1];      // 8.125 KB
        float sV[32][CC];          // 8 KB
        float sS[32][33];          // 4.125 KB
        float sm[32], sl[32], sfac[32];
    } sp;
    struct {                       // channel attention
        float sq[CC][33];          // 8.25 KB (also reused for V tile)
        float sk[CC][33];          // 8.25 KB
        float satt[CC][CC + 1];    // 16.25 KB
    } ch;
};

// ---------------------------------------------------------------------------
__global__ void __launch_bounds__(TPB, 2)
pcam_fused(const float* __restrict__ x,
           const float* __restrict__ wqs, const float* __restrict__ bqs,
           const float* __restrict__ wks, const float* __restrict__ bks,
           const float* __restrict__ wvs, const float* __restrict__ bvs,
           const float* __restrict__ wqc, const float* __restrict__ bqc,
           const float* __restrict__ wkc, const float* __restrict__ bkc,
           const float* __restrict__ wvc, const float* __restrict__ bvc,
           const float* __restrict__ ga, const float* __restrict__ gb,
           float* __restrict__ out)
{
    const int t   = threadIdx.x;
    const int bid = blockIdx.x;
    const int tid = bid * TPB + t;      // 0..75775

    __shared__ float s_gates[2];

    // ONE thread per block reads the gate scalars (592 same-address L2
    // requests chip-wide instead of ~4700 warp-level ones), while every
    // thread's copy stream proceeds gate-independently below.
    if (t == 0) {
        s_gates[0] = __ldg(ga);
        s_gates[1] = __ldg(gb);
    }

    const float4* __restrict__ x4 = reinterpret_cast<const float4*>(x);
    float4* __restrict__ o4 = reinterpret_cast<float4*>(out);

    // Gate-independent speculative copy: out = 2x, issued before the gates
    // are even known. k=0..2 always in range (227327 < NV); k=3 partial.
    const bool p3 = (tid + 3 * STRIDE) < NV;
    const float4 v0 = x4[tid];
    const float4 v1 = x4[tid + STRIDE];
    const float4 v2 = x4[tid + 2 * STRIDE];
    const float4 v3 = p3 ? x4[tid + 3 * STRIDE] : make_float4(0.f, 0.f, 0.f, 0.f);

    // SPECULATIVE STORE: if gates are nonzero, the heavy path's fuse phase
    // overwrites every element; nothing reads `out` in between.
    __stwt(&o4[tid],              make_float4(2.f*v0.x, 2.f*v0.y, 2.f*v0.z, 2.f*v0.w));
    __stwt(&o4[tid + STRIDE],     make_float4(2.f*v1.x, 2.f*v1.y, 2.f*v1.z, 2.f*v1.w));
    __stwt(&o4[tid + 2 * STRIDE], make_float4(2.f*v2.x, 2.f*v2.y, 2.f*v2.z, 2.f*v2.w));
    if (p3)
        __stwt(&o4[tid + 3 * STRIDE], make_float4(2.f*v3.x, 2.f*v3.y, 2.f*v3.z, 2.f*v3.w));

    // Resolve gates via shared-memory broadcast (cheap, off the store path).
    __syncthreads();
    const float av = s_gates[0];
    const float bv = s_gates[1];
    const bool need_s = (bv != 0.0f);
    const bool need_c = (av != 0.0f);
    if (!need_s && !need_c) return;     // fast path done

    // ======================= HEAVY PATH ====================================
    __shared__ SmemU u;

    // ---- Phase 1: six 1x1-conv projections, y = x @ W + bias -------------
    {
        const float* Ws[6] = {wqs, wks, wvs, wqc, wkc, wvc};
        const float* Bs[6] = {bqs, bks, bvs, bqc, bkc, bvc};
        float* Os[6] = {g_qs, g_ks, g_vs, g_qc, g_kc, g_vc};

        const int d  = t & 63;
        const int r0 = t >> 6;

        for (int chunk = bid; chunk < ROWS / 64; chunk += GRID) {
            const int row0 = chunk * 64;
            __syncthreads();
            for (int i = t; i < 64 * CC; i += TPB)
                u.pr.sx[i / CC][i % CC] = x[row0 * CC + i];

            for (int p = 0; p < 6; p++) {
                const bool need = (p < 3) ? need_s : need_c;   // uniform
                if (!need) continue;
                __syncthreads();
                for (int i = t; i < CC * CC; i += TPB)
                    u.pr.sw[i / CC][i % CC] = Ws[p][i];
                if (t < CC) u.pr.sb[t] = Bs[p][t];
                __syncthreads();
                #pragma unroll
                for (int i = 0; i < 16; i++) {
                    const int r = r0 + 4 * i;
                    float s = u.pr.sb[d];
                    #pragma unroll
                    for (int c = 0; c < CC; c++)
                        s = fmaf(u.pr.sx[r][c], u.pr.sw[c][d], s);
                    Os[p][(row0 + r) * CC + d] = s;
                }
            }
        }
    }
    grid_sync();

    // ---- Phase 2a: spatial flash attention (512 tiles of 32 rows) --------
    if (need_s) {
        const int kS  = t & 31;
        const int rS0 = t >> 5;
        const int dO  = t & 63;
        const int rO0 = t >> 6;

        for (int tile = bid; tile < (NN / 32) * BB; tile += GRID) {
            const int bb    = tile >> 7;           // tile / 128
            const int rbase = (tile & 127) * 32;
            const float* Qg = g_qs + (bb * NN + rbase) * CC;
            const float* Kg = g_ks + bb * NN * CC;
            const float* Vg = g_vs + bb * NN * CC;

            __syncthreads();
            for (int i = t; i < 32 * CC; i += TPB)
                u.sp.sQ[i / CC][i % CC] = Qg[i];
            if (t < 32) { u.sp.sm[t] = -1e30f; u.sp.sl[t] = 0.0f; }

            float accO[8];
            #pragma unroll
            for (int i = 0; i < 8; i++) accO[i] = 0.0f;
            __syncthreads();

            for (int k0 = 0; k0 < NN; k0 += 32) {
                for (int i = t; i < 32 * CC; i += TPB) {
                    const int kr = i / CC, c = i % CC;
                    u.sp.sK[kr][c] = Kg[(k0 + kr) * CC + c];
                    u.sp.sV[kr][c] = Vg[(k0 + kr) * CC + c];
                }
                __syncthreads();

                #pragma unroll
                for (int i = 0; i < 4; i++) {
                    const int r = rS0 + 8 * i;
                    float s = 0.0f;
                    #pragma unroll
                    for (int c = 0; c < CC; c++)
                        s = fmaf(u.sp.sQ[r][c], u.sp.sK[kS][c], s);
                    u.sp.sS[r][kS] = s * 0.125f;
                }
                __syncthreads();

                if (t < 32) {
                    float mx = u.sp.sm[t];
                    #pragma unroll
                    for (int k = 0; k < 32; k++) mx = fmaxf(mx, u.sp.sS[t][k]);
                    const float fac = __expf(u.sp.sm[t] - mx);
                    float lsum = u.sp.sl[t] * fac;
                    #pragma unroll
                    for (int k = 0; k < 32; k++) {
                        const float p = __expf(u.sp.sS[t][k] - mx);
                        u.sp.sS[t][k] = p;
                        lsum += p;
                    }
                    u.sp.sm[t] = mx; u.sp.sl[t] = lsum; u.sp.sfac[t] = fac;
                }
                __syncthreads();

                #pragma unroll
                for (int i = 0; i < 8; i++) {
                    const int r = rO0 + 4 * i;
                    float s = 0.0f;
                    #pragma unroll
                    for (int k = 0; k < 32; k++)
                        s = fmaf(u.sp.sS[r][k], u.sp.sV[k][dO], s);
                    accO[i] = accO[i] * u.sp.sfac[r] + s;
                }
                __syncthreads();
            }

            #pragma unroll
            for (int i = 0; i < 8; i++) {
                const int r = rO0 + 4 * i;
                g_spat[(bb * NN + rbase + r) * CC + dO] = accO[i] / u.sp.sl[r];
            }
        }
    }

    // ---- Phase 2b: channel attention (one block per batch) ---------------
    if (need_c && bid < BB) {
        const int bb = bid;
        const float* qc = g_qc + bb * NN * CC;
        const float* kc = g_kc + bb * NN * CC;
        const float* vc = g_vc + bb * NN * CC;
        float* chan = g_chan + bb * NN * CC;

        const int d  = t & 63;
        const int c0 = t >> 6;

        float acc[16];
        #pragma unroll
        for (int i = 0; i < 16; i++) acc[i] = 0.0f;

        // Gram: G[c][d] = sum_n qc[c,n] * kc[d,n]
        for (int n0 = 0; n0 < NN; n0 += 32) {
            __syncthreads();
            for (int i = t; i < CC * 32; i += TPB) {
                const int c = i >> 5, j = i & 31;
                u.ch.sq[c][j] = qc[c * NN + n0 + j];
                u.ch.sk[c][j] = kc[c * NN + n0 + j];
            }
            __syncthreads();
            #pragma unroll
            for (int i = 0; i < 16; i++) {
                const int c = c0 + 4 * i;
                float s = 0.0f;
                #pragma unroll
                for (int j = 0; j < 32; j++)
                    s = fmaf(u.ch.sq[c][j], u.ch.sk[d][j], s);
                acc[i] += s;
            }
        }
        __syncthreads();
        #pragma unroll
        for (int i = 0; i < 16; i++) u.ch.satt[c0 + 4 * i][d] = acc[i] * 0.125f;
        __syncthreads();

        if (t < CC) {
            float mx = -1e30f;
            for (int dd = 0; dd < CC; dd++) mx = fmaxf(mx, u.ch.satt[t][dd]);
            float sum = 0.0f;
            for (int dd = 0; dd < CC; dd++) {
                const float p = __expf(u.ch.satt[t][dd] - mx);
                u.ch.satt[t][dd] = p; sum += p;
            }
            const float inv = 1.0f / sum;
            for (int dd = 0; dd < CC; dd++) u.ch.satt[t][dd] *= inv;
        }
        __syncthreads();

        const int j   = t & 31;
        const int c0b = t >> 5;
        for (int n0 = 0; n0 < NN; n0 += 32) {
            __syncthreads();
            for (int i = t; i < CC * 32; i += TPB) {
                const int dd = i >> 5, jj = i & 31;
                u.ch.sq[dd][jj] = vc[dd * NN + n0 + jj];
            }
            __syncthreads();
            #pragma unroll
            for (int i = 0; i < 8; i++) {
                const int c = c0b + 8 * i;
                float s = 0.0f;
                #pragma unroll
                for (int dd = 0; dd < CC; dd++)
                    s = fmaf(u.ch.satt[c][dd], u.ch.sq[dd][j], s);
                chan[c * NN + n0 + j] = s;
            }
        }
    }
    grid_sync();

    // ---- Phase 3: fuse out = 2x + b*spat + a*chan -------------------------
    // Overwrites the speculative 2x stores with the full result.
    // (channel's raw (B,C,N)->(B,H,W,C) reshape is a flat no-op)
    const float4* s4 = reinterpret_cast<const float4*>(g_spat);
    const float4* c4 = reinterpret_cast<const float4*>(g_chan);
    #pragma unroll
    for (int k = 0; k < 4; k++) {
        const int i = tid + k * STRIDE;
        if (i >= NV) break;
        const float4 xv = x4[i];
        float4 o = make_float4(2.0f * xv.x, 2.0f * xv.y, 2.0f * xv.z, 2.0f * xv.w);
        if (need_s) {
            const float4 s = s4[i];
            o.x += bv * s.x; o.y += bv * s.y; o.z += bv * s.z; o.w += bv * s.w;
        }
        if (need_c) {
            const float4 c = c4[i];
            o.x += av * c.x; o.y += av * c.y; o.z += av * c.z; o.w += av * c.w;
        }
        __stwt(&o4[i], o);
    }
}

// ---------------------------------------------------------------------------
extern "C" void kernel_launch(void* const* d_in, const int* in_sizes, int n_in,
                              void* d_out, int out_size)
{
    const float* x   = (const float*)d_in[0];
    const float* wqs = (const float*)d_in[1];  const float* bqs = (const float*)d_in[2];
    const float* wks = (const float*)d_in[3];  const float* bks = (const float*)d_in[4];
    const float* wvs = (const float*)d_in[5];  const float* bvs = (const float*)d_in[6];
    const float* wqc = (const float*)d_in[7];  const float* bqc = (const float*)d_in[8];
    const float* wkc = (const float*)d_in[9];  const float* bkc = (const float*)d_in[10];
    const float* wvc = (const float*)d_in[11]; const float* bvc = (const float*)d_in[12];
    const float* ga  = (const float*)d_in[13];
    const float* gb  = (const float*)d_in[14];

    pcam_fused<<<GRID, TPB>>>(x, wqs, bqs, wks, bks, wvs, bvs,
                              wqc, bqc, wkc, bkc, wvc, bvc,
                              ga, gb, (float*)d_out);
}